// round 1
// baseline (speedup 1.0000x reference)
#include <cuda_runtime.h>
#include <math.h>

#define THREADS 256

// ---------------- device-global precomputed weights (scratch; no allocation) ----
__device__ float g_R0[64 * 64];
__device__ float g_R1[48 * 48];
__device__ float g_M0[64 * 56];     // R0^T @ t0_w1
__device__ float g_M1[48 * 40];     // R1^T @ t1_w1
__device__ float g_Wfold[784 * 64]; // W_in @ W_tan
__device__ float g_bfold[64];       // b_in @ W_tan + b_tan

// ================= expm of skew(A) via scaling-and-squaring Taylor =============
// block 0: 64x64 from A0 ; block 1: 48x48 from A1
__global__ void __launch_bounds__(THREADS) expm_kernel(const float* __restrict__ A0,
                                                       const float* __restrict__ A1)
{
    __shared__ float T[4096];
    __shared__ float P[4096];
    __shared__ float E[4096];
    int n; const float* A; float* R;
    if (blockIdx.x == 0) { n = 64; A = A0; R = g_R0; }
    else                 { n = 48; A = A1; R = g_R1; }
    const int tid = threadIdx.x;
    const int nn = n * n;

    // S = A - A^T (unscaled) into T
    for (int i = tid; i < nn; i += THREADS) {
        int r = i / n, c = i - r * n;
        T[i] = A[r * n + c] - A[c * n + r];
    }
    __syncthreads();
    // inf-norm (row abs-sums into P[0..n))
    if (tid < n) {
        float s = 0.f;
        for (int c = 0; c < n; c++) s += fabsf(T[tid * n + c]);
        P[tid] = s;
    }
    __syncthreads();
    if (tid == 0) {
        float m = 0.f;
        for (int r = 0; r < n; r++) m = fmaxf(m, P[r]);
        int sh = 0;
        while (m > 0.25f && sh < 40) { m *= 0.5f; sh++; }
        P[64] = (float)sh;
    }
    __syncthreads();
    const int shift = (int)P[64];
    const float sc = ldexpf(1.0f, -shift);
    __syncthreads();
    // T scaled, P = T, E = I + T
    for (int i = tid; i < nn; i += THREADS) {
        float t = T[i] * sc;
        int r = i / n, c = i - r * n;
        T[i] = t; P[i] = t;
        E[i] = t + (r == c ? 1.0f : 0.0f);
    }
    __syncthreads();
    // Taylor terms 2..14
    for (int k = 2; k <= 14; k++) {
        float tmp[16]; int cnt = 0;
        for (int i = tid; i < nn; i += THREADS) {
            int r = i / n, c = i - r * n;
            float s = 0.f;
            for (int j = 0; j < n; j++) s += P[r * n + j] * T[j * n + c];
            tmp[cnt++] = s / (float)k;
        }
        __syncthreads();
        cnt = 0;
        for (int i = tid; i < nn; i += THREADS) { P[i] = tmp[cnt]; E[i] += tmp[cnt]; cnt++; }
        __syncthreads();
    }
    // squarings
    for (int sq = 0; sq < shift; sq++) {
        float tmp[16]; int cnt = 0;
        for (int i = tid; i < nn; i += THREADS) {
            int r = i / n, c = i - r * n;
            float s = 0.f;
            for (int j = 0; j < n; j++) s += E[r * n + j] * E[j * n + c];
            tmp[cnt++] = s;
        }
        __syncthreads();
        cnt = 0;
        for (int i = tid; i < nn; i += THREADS) E[i] = tmp[cnt++];
        __syncthreads();
    }
    for (int i = tid; i < nn; i += THREADS) R[i] = E[i];
}

// ============ prep2: fold weights  (needs g_R0/g_R1 done) ======================
__global__ void __launch_bounds__(THREADS) prep2_kernel(
    const float* __restrict__ W_in, const float* __restrict__ b_in,
    const float* __restrict__ W_tan, const float* __restrict__ b_tan,
    const float* __restrict__ t0w1, const float* __restrict__ t1w1)
{
    const int bid = blockIdx.x, tid = threadIdx.x;
    if (bid == 0) {
        // M0[i][m] = sum_j R0[j][i] * t0w1[j][m]   (64 x 56)
        for (int i = tid; i < 64 * 56; i += THREADS) {
            int r = i / 56, m = i - r * 56;
            float s = 0.f;
            for (int j = 0; j < 64; j++) s += g_R0[j * 64 + r] * t0w1[j * 56 + m];
            g_M0[i] = s;
        }
    } else if (bid == 1) {
        // M1[i][m] = sum_j R1[j][i] * t1w1[j][m]   (48 x 40)
        for (int i = tid; i < 48 * 40; i += THREADS) {
            int r = i / 40, m = i - r * 40;
            float s = 0.f;
            for (int j = 0; j < 48; j++) s += g_R1[j * 48 + r] * t1w1[j * 40 + m];
            g_M1[i] = s;
        }
        // bfold[c] = b_in @ W_tan + b_tan
        for (int c = tid; c < 64; c += THREADS) {
            float s = b_tan[c];
            for (int j = 0; j < 128; j++) s += b_in[j] * W_tan[j * 64 + c];
            g_bfold[c] = s;
        }
    } else {
        int idx = (bid - 2) * THREADS + tid;
        if (idx < 784 * 64) {
            int k = idx / 64, c = idx - k * 64;
            float s = 0.f;
            for (int j = 0; j < 128; j++) s += W_in[k * 128 + j] * W_tan[j * 64 + c];
            g_Wfold[idx] = s;
        }
    }
}

// ===================== level scalar gain =======================================
// v_out = g(||v||) * v, mirroring reference fp32 rounding structure.
__device__ __forceinline__ float level_g(float rf, float sqcf, float s_raw, float smin)
{
    float scale = fmaxf(s_raw, smin);
    float ut = scale * rf;                  // true ||u||
    float un = fmaxf(ut, 1e-7f);
    float th = tanhf(sqcf * un);
    float a  = th / (sqcf * un);            // expmap0 factor
    float en = fmaxf(a * ut, 1e-7f);        // ||e||
    float maxn = 0.99999f / sqcf;
    float f  = fminf(1.0f, maxn / en);      // projx factor
    float xn = fmaxf(f * (a * ut), 1e-7f);  // ||xh||
    float arg = fminf(sqcf * xn, 0.99999994f);
    double L = atanh((double)arg) / ((double)sqcf * (double)xn);  // logmap0 factor
    return (float)(L * (double)f * (double)a * (double)scale / (double)(scale + 1e-7f));
}

// ===================== smem layout (floats) ====================================
#define OFF_M0   0
#define OFF_B1   3584
#define OFF_W2   3640
#define OFF_B2   6328
#define OFF_M1   6376
#define OFF_B1B  8296
#define OFF_W2B  8336
#define OFF_B2B  9616
#define OFF_WOUT 9648      /* 144 x 12 (cols padded) */
#define OFF_BOUT 11376
#define OFF_BF   11388
#define OFF_G    11452
#define OFF_V0   11516     /* 64 x 65 */
#define OFF_C    15676
#define OFF_XS   (OFF_C)               /* 56 x 68 transposed x tile */
#define OFF_WS   (OFF_C + 3808)        /* 56 x 64 W tile */
#define OFF_H    (OFF_C)               /* h56 (64x56) / h40 (64x40) */
#define OFF_V1   (OFF_C + 3584)        /* 64 x 49 */
#define OFF_V2   (OFF_V1 + 3136)       /* 64 x 33 */
#define OFF_OUT  (OFF_V2 + 2112)       /* 64 x 12 */
#define SMEM_FLOATS (OFF_OUT + 768)
#define SMEM_BYTES (SMEM_FLOATS * 4)

// ===================== smem mat-mat helper (64 rows) ===========================
__device__ __forceinline__ void matvec_tile(
    const float* __restrict__ in, int instr, int K,
    const float* __restrict__ W, int N,
    const float* __restrict__ bias,
    float* __restrict__ out, int outstr,
    bool relu, bool accum, int tid)
{
    const int CT = N >> 2;
    const int rt = tid / CT;
    if (rt >= 16) return;
    const int ct = tid - rt * CT;
    float acc[4][4];
    if (accum) {
        #pragma unroll
        for (int i = 0; i < 4; i++)
            #pragma unroll
            for (int j = 0; j < 4; j++)
                acc[i][j] = out[(4 * rt + i) * outstr + 4 * ct + j];
    } else {
        #pragma unroll
        for (int i = 0; i < 4; i++)
            #pragma unroll
            for (int j = 0; j < 4; j++) acc[i][j] = 0.f;
    }
    const float* inr0 = in + (4 * rt + 0) * instr;
    const float* inr1 = in + (4 * rt + 1) * instr;
    const float* inr2 = in + (4 * rt + 2) * instr;
    const float* inr3 = in + (4 * rt + 3) * instr;
    #pragma unroll 4
    for (int k = 0; k < K; k++) {
        float a0 = inr0[k], a1 = inr1[k], a2 = inr2[k], a3 = inr3[k];
        float4 w = *(const float4*)(W + k * N + 4 * ct);
        acc[0][0] += a0 * w.x; acc[0][1] += a0 * w.y; acc[0][2] += a0 * w.z; acc[0][3] += a0 * w.w;
        acc[1][0] += a1 * w.x; acc[1][1] += a1 * w.y; acc[1][2] += a1 * w.z; acc[1][3] += a1 * w.w;
        acc[2][0] += a2 * w.x; acc[2][1] += a2 * w.y; acc[2][2] += a2 * w.z; acc[2][3] += a2 * w.w;
        acc[3][0] += a3 * w.x; acc[3][1] += a3 * w.y; acc[3][2] += a3 * w.z; acc[3][3] += a3 * w.w;
    }
    #pragma unroll
    for (int i = 0; i < 4; i++)
        #pragma unroll
        for (int j = 0; j < 4; j++) {
            float v = acc[i][j];
            if (bias) v += bias[4 * ct + j];
            if (relu) v = fmaxf(v, 0.f);
            out[(4 * rt + i) * outstr + 4 * ct + j] = v;
        }
}

// ===================== main fused kernel: 64 rows / block ======================
__global__ void __launch_bounds__(THREADS) main_kernel(
    const float* __restrict__ x,
    const float* __restrict__ s0p, const float* __restrict__ s1p, const float* __restrict__ s2p,
    const float* __restrict__ t0b1, const float* __restrict__ t0w2, const float* __restrict__ t0b2,
    const float* __restrict__ t1b1, const float* __restrict__ t1w2, const float* __restrict__ t1b2,
    const float* __restrict__ Wout, const float* __restrict__ bout,
    float* __restrict__ out, int B)
{
    extern __shared__ float sm[];
    const int tid = threadIdx.x;
    const int row0 = blockIdx.x * 64;

    // ---- load small weights into smem --------------------------------------
    for (int i = tid; i < 3584; i += THREADS) sm[OFF_M0 + i] = g_M0[i];
    for (int i = tid; i < 56;   i += THREADS) sm[OFF_B1 + i] = t0b1[i];
    for (int i = tid; i < 2688; i += THREADS) sm[OFF_W2 + i] = t0w2[i];
    for (int i = tid; i < 48;   i += THREADS) sm[OFF_B2 + i] = t0b2[i];
    for (int i = tid; i < 1920; i += THREADS) sm[OFF_M1 + i] = g_M1[i];
    for (int i = tid; i < 40;   i += THREADS) sm[OFF_B1B + i] = t1b1[i];
    for (int i = tid; i < 1280; i += THREADS) sm[OFF_W2B + i] = t1w2[i];
    for (int i = tid; i < 32;   i += THREADS) sm[OFF_B2B + i] = t1b2[i];
    for (int i = tid; i < 144 * 12; i += THREADS) {
        int k = i / 12, c = i - k * 12;
        sm[OFF_WOUT + i] = (c < 10) ? Wout[k * 10 + c] : 0.f;
    }
    for (int i = tid; i < 12; i += THREADS) sm[OFF_BOUT + i] = (i < 10) ? bout[i] : 0.f;
    for (int i = tid; i < 64; i += THREADS) sm[OFF_BF + i] = g_bfold[i];

    // ---- big GEMM: v = x @ Wfold + bfold  (64x784 @ 784x64) -----------------
    float acc[4][4];
    #pragma unroll
    for (int i = 0; i < 4; i++)
        #pragma unroll
        for (int j = 0; j < 4; j++) acc[i][j] = 0.f;
    const int ty = tid >> 4, tx = tid & 15;

    for (int kt = 0; kt < 14; kt++) {
        __syncthreads();
        const int kbase = kt * 56;
        for (int i = tid; i < 64 * 56; i += THREADS) {
            int r = i / 56, k = i - r * 56;
            int gr = row0 + r;
            sm[OFF_XS + k * 68 + r] = (gr < B) ? x[(size_t)gr * 784 + kbase + k] : 0.f;
        }
        for (int i = tid; i < 56 * 64; i += THREADS) {
            sm[OFF_WS + i] = g_Wfold[kbase * 64 + i];
        }
        __syncthreads();
        #pragma unroll 4
        for (int k = 0; k < 56; k++) {
            float4 a = *(const float4*)(sm + OFF_XS + k * 68 + 4 * ty);
            float4 b = *(const float4*)(sm + OFF_WS + k * 64 + 4 * tx);
            acc[0][0] += a.x * b.x; acc[0][1] += a.x * b.y; acc[0][2] += a.x * b.z; acc[0][3] += a.x * b.w;
            acc[1][0] += a.y * b.x; acc[1][1] += a.y * b.y; acc[1][2] += a.y * b.z; acc[1][3] += a.y * b.w;
            acc[2][0] += a.z * b.x; acc[2][1] += a.z * b.y; acc[2][2] += a.z * b.z; acc[2][3] += a.z * b.w;
            acc[3][0] += a.w * b.x; acc[3][1] += a.w * b.y; acc[3][2] += a.w * b.z; acc[3][3] += a.w * b.w;
        }
    }
    __syncthreads();
    #pragma unroll
    for (int i = 0; i < 4; i++)
        #pragma unroll
        for (int j = 0; j < 4; j++)
            sm[OFF_V0 + (4 * ty + i) * 65 + 4 * tx + j] = acc[i][j] + sm[OFF_BF + 4 * tx + j];
    __syncthreads();

    const float s0 = s0p[0], s1 = s1p[0], s2 = s2p[0];

    // ---- level 0 (c=1.0) -----------------------------------------------------
    if (tid < 64) {
        double r2 = 0.0;
        for (int k = 0; k < 64; k++) { float d = sm[OFF_V0 + tid * 65 + k]; r2 += (double)d * (double)d; }
        sm[OFF_G + tid] = level_g((float)sqrt(r2), 1.0f, s0, 1e-4f);
    }
    __syncthreads();
    for (int i = tid; i < 64 * 64; i += THREADS) {
        int r = i >> 6;
        sm[OFF_V0 + r * 65 + (i & 63)] *= sm[OFF_G + r];
    }
    __syncthreads();

    // ---- MLP0 (rotation folded into M0) -------------------------------------
    matvec_tile(sm + OFF_V0, 65, 64, sm + OFF_M0, 56, sm + OFF_B1, sm + OFF_H, 56, true,  false, tid);
    __syncthreads();
    matvec_tile(sm + OFF_H, 56, 56, sm + OFF_W2, 48, sm + OFF_B2, sm + OFF_V1, 49, false, false, tid);
    __syncthreads();

    // ---- level 1 (c=0.8) -----------------------------------------------------
    if (tid < 64) {
        double r2 = 0.0;
        for (int k = 0; k < 48; k++) { float d = sm[OFF_V1 + tid * 49 + k]; r2 += (double)d * (double)d; }
        sm[OFF_G + tid] = level_g((float)sqrt(r2), sqrtf(0.8f), s1, 1e-5f);
    }
    __syncthreads();
    for (int i = tid; i < 64 * 48; i += THREADS) {
        int r = i / 48;
        sm[OFF_V1 + r * 49 + (i - r * 48)] *= sm[OFF_G + r];
    }
    __syncthreads();

    // ---- MLP1 ----------------------------------------------------------------
    matvec_tile(sm + OFF_V1, 49, 48, sm + OFF_M1, 40, sm + OFF_B1B, sm + OFF_H, 40, true,  false, tid);
    __syncthreads();
    matvec_tile(sm + OFF_H, 40, 40, sm + OFF_W2B, 32, sm + OFF_B2B, sm + OFF_V2, 33, false, false, tid);
    __syncthreads();

    // ---- level 2 (c=1.2) -----------------------------------------------------
    if (tid < 64) {
        double r2 = 0.0;
        for (int k = 0; k < 32; k++) { float d = sm[OFF_V2 + tid * 33 + k]; r2 += (double)d * (double)d; }
        sm[OFF_G + tid] = level_g((float)sqrt(r2), sqrtf(1.2f), s2, 1e-6f);
    }
    __syncthreads();
    for (int i = tid; i < 64 * 32; i += THREADS) {
        int r = i >> 5;
        sm[OFF_V2 + r * 33 + (i & 31)] *= sm[OFF_G + r];
    }
    __syncthreads();

    // ---- final projection: out = [v0 v1 v2] @ Wout + bout ---------------------
    matvec_tile(sm + OFF_V0, 65, 64, sm + OFF_WOUT,            12, sm + OFF_BOUT, sm + OFF_OUT, 12, false, false, tid);
    __syncthreads();
    matvec_tile(sm + OFF_V1, 49, 48, sm + OFF_WOUT + 64 * 12,  12, (const float*)0, sm + OFF_OUT, 12, false, true, tid);
    __syncthreads();
    matvec_tile(sm + OFF_V2, 33, 32, sm + OFF_WOUT + 112 * 12, 12, (const float*)0, sm + OFF_OUT, 12, false, true, tid);
    __syncthreads();

    for (int i = tid; i < 640; i += THREADS) {
        int r = i / 10, c = i - r * 10;
        int gr = row0 + r;
        if (gr < B) out[(size_t)gr * 10 + c] = sm[OFF_OUT + r * 12 + c];
    }
}

// =========================== launch ===========================================
extern "C" void kernel_launch(void* const* d_in, const int* in_sizes, int n_in,
                              void* d_out, int out_size)
{
    const float* x     = (const float*)d_in[0];
    const float* W_in  = (const float*)d_in[1];
    const float* b_in  = (const float*)d_in[2];
    const float* W_tan = (const float*)d_in[3];
    const float* b_tan = (const float*)d_in[4];
    const float* s0    = (const float*)d_in[5];
    const float* s1    = (const float*)d_in[6];
    const float* s2    = (const float*)d_in[7];
    // d_in[8], d_in[9]: tp0/tp1 boundary params — dead path, unused
    const float* A0    = (const float*)d_in[10];
    const float* A1    = (const float*)d_in[11];
    const float* t0w1  = (const float*)d_in[12];
    const float* t0b1  = (const float*)d_in[13];
    const float* t0w2  = (const float*)d_in[14];
    const float* t0b2  = (const float*)d_in[15];
    const float* t1w1  = (const float*)d_in[16];
    const float* t1b1  = (const float*)d_in[17];
    const float* t1w2  = (const float*)d_in[18];
    const float* t1b2  = (const float*)d_in[19];
    const float* Wout  = (const float*)d_in[20];
    const float* bout  = (const float*)d_in[21];
    float* out = (float*)d_out;

    const int B = in_sizes[0] / 784;

    cudaFuncSetAttribute(main_kernel, cudaFuncAttributeMaxDynamicSharedMemorySize, SMEM_BYTES);

    expm_kernel<<<2, THREADS>>>(A0, A1);
    prep2_kernel<<<2 + (784 * 64 + THREADS - 1) / THREADS, THREADS>>>(W_in, b_in, W_tan, b_tan, t0w1, t1w1);
    main_kernel<<<(B + 63) / 64, THREADS, SMEM_BYTES>>>(
        x, s0, s1, s2, t0b1, t0w2, t0b2, t1b1, t1w2, t1b2, Wout, bout, out, B);
}

// round 3
// speedup vs baseline: 1.7599x; 1.7599x over previous
#include <cuda_runtime.h>
#include <math.h>

#define THREADS 256

// ---------------- device-global precomputed weights (scratch; no allocation) ----
__device__ __align__(16) float g_M0[64 * 56];     // R0^T @ t0_w1
__device__ __align__(16) float g_M1[48 * 40];     // R1^T @ t1_w1
__device__ __align__(16) float g_Wfold[784 * 64]; // W_in @ W_tan
__device__ __align__(16) float g_bfold[64];       // b_in @ W_tan + b_tan

// ---------------- cp.async helpers ---------------------------------------------
#define CP16(dst_smem, src_gmem) \
    asm volatile("cp.async.cg.shared.global [%0], [%1], 16;\n" :: "r"(dst_smem), "l"(src_gmem))
#define CP_COMMIT() asm volatile("cp.async.commit_group;\n")
#define CP_WAIT1()  asm volatile("cp.async.wait_group 1;\n")
#define CP_WAIT0()  asm volatile("cp.async.wait_group 0;\n")

// =========== prep: expm+fold (blocks 0,1) and Wfold/bfold (blocks 2+) ==========
__global__ void __launch_bounds__(THREADS) prep_kernel(
    const float* __restrict__ A0, const float* __restrict__ A1,
    const float* __restrict__ t0w1, const float* __restrict__ t1w1,
    const float* __restrict__ W_in, const float* __restrict__ b_in,
    const float* __restrict__ W_tan, const float* __restrict__ b_tan)
{
    const int tid = threadIdx.x;
    if (blockIdx.x >= 2) {
        // ---- Wfold: W_in(784x128) @ W_tan(128x64) -----------------------------
        int idx = (blockIdx.x - 2) * THREADS + tid;
        if (idx < 784 * 64) {
            int k = idx >> 6, c = idx & 63;
            float s = 0.f;
            #pragma unroll 8
            for (int j = 0; j < 128; j++)
                s += __ldg(W_in + k * 128 + j) * __ldg(W_tan + j * 64 + c);
            g_Wfold[idx] = s;
        }
        if (blockIdx.x == 2 && tid < 64) {
            float s = b_tan[tid];
            for (int j = 0; j < 128; j++) s += b_in[j] * W_tan[j * 64 + tid];
            g_bfold[tid] = s;
        }
        return;
    }

    // ---- expm of skew(A) via scaling-and-squaring Taylor (register-tiled) ----
    __shared__ __align__(16) float T[4096];
    __shared__ __align__(16) float P[4096];
    __shared__ __align__(16) float E[4096];
    const int n = (blockIdx.x == 0) ? 64 : 48;
    const float* A = (blockIdx.x == 0) ? A0 : A1;
    const int nn = n * n;

    for (int i = tid; i < nn; i += THREADS) {
        int r = i / n, c = i - r * n;
        T[i] = A[r * n + c] - A[c * n + r];
    }
    __syncthreads();
    if (tid < n) {
        float s = 0.f;
        for (int c = 0; c < n; c++) s += fabsf(T[tid * n + c]);
        P[tid] = s;
    }
    __syncthreads();
    // every thread redundantly computes the shift (deterministic, no extra smem)
    int shift;
    {
        float m = 0.f;
        for (int r = 0; r < n; r++) m = fmaxf(m, P[r]);
        int sh = 0;
        while (m > 0.25f && sh < 30) { m *= 0.5f; sh++; }
        shift = sh;
    }
    __syncthreads();
    const float sc = ldexpf(1.0f, -shift);
    for (int i = tid; i < nn; i += THREADS) {
        float t = T[i] * sc;
        int r = i / n, c = i - r * n;
        T[i] = t; P[i] = t;
        E[i] = t + (r == c ? 1.0f : 0.0f);
    }
    __syncthreads();

    const int RT = n >> 2;
    const int rt = tid / RT, ct = tid - rt * RT;
    const bool act = (rt < RT);
    const int rbase = 4 * rt, cbase = 4 * ct;

    // Taylor terms 2..10
    for (int term = 2; term <= 10; term++) {
        float acc[4][4] = {};
        if (act) {
            for (int kk = 0; kk < n; kk++) {
                float4 b = *(const float4*)(T + kk * n + cbase);
                float a0 = P[(rbase + 0) * n + kk];
                float a1 = P[(rbase + 1) * n + kk];
                float a2 = P[(rbase + 2) * n + kk];
                float a3 = P[(rbase + 3) * n + kk];
                acc[0][0] += a0*b.x; acc[0][1] += a0*b.y; acc[0][2] += a0*b.z; acc[0][3] += a0*b.w;
                acc[1][0] += a1*b.x; acc[1][1] += a1*b.y; acc[1][2] += a1*b.z; acc[1][3] += a1*b.w;
                acc[2][0] += a2*b.x; acc[2][1] += a2*b.y; acc[2][2] += a2*b.z; acc[2][3] += a2*b.w;
                acc[3][0] += a3*b.x; acc[3][1] += a3*b.y; acc[3][2] += a3*b.z; acc[3][3] += a3*b.w;
            }
        }
        __syncthreads();
        if (act) {
            float inv = 1.0f / (float)term;
            #pragma unroll
            for (int i = 0; i < 4; i++)
                #pragma unroll
                for (int j = 0; j < 4; j++) {
                    float v = acc[i][j] * inv;
                    P[(rbase + i) * n + cbase + j] = v;
                    E[(rbase + i) * n + cbase + j] += v;
                }
        }
        __syncthreads();
    }
    // squarings
    for (int sq = 0; sq < shift; sq++) {
        float acc[4][4] = {};
        if (act) {
            for (int kk = 0; kk < n; kk++) {
                float4 b = *(const float4*)(E + kk * n + cbase);
                float a0 = E[(rbase + 0) * n + kk];
                float a1 = E[(rbase + 1) * n + kk];
                float a2 = E[(rbase + 2) * n + kk];
                float a3 = E[(rbase + 3) * n + kk];
                acc[0][0] += a0*b.x; acc[0][1] += a0*b.y; acc[0][2] += a0*b.z; acc[0][3] += a0*b.w;
                acc[1][0] += a1*b.x; acc[1][1] += a1*b.y; acc[1][2] += a1*b.z; acc[1][3] += a1*b.w;
                acc[2][0] += a2*b.x; acc[2][1] += a2*b.y; acc[2][2] += a2*b.z; acc[2][3] += a2*b.w;
                acc[3][0] += a3*b.x; acc[3][1] += a3*b.y; acc[3][2] += a3*b.z; acc[3][3] += a3*b.w;
            }
        }
        __syncthreads();
        if (act) {
            #pragma unroll
            for (int i = 0; i < 4; i++)
                #pragma unroll
                for (int j = 0; j < 4; j++)
                    E[(rbase + i) * n + cbase + j] = acc[i][j];
        }
        __syncthreads();
    }

    // ---- fold: M = R^T @ w1  (R = E) ------------------------------------------
    if (blockIdx.x == 0) {
        // M0[64][56]
        const int CT2 = 14;
        int rt2 = tid / CT2, ct2 = tid - rt2 * CT2;
        if (rt2 < 16) {
            float acc[4][4] = {};
            for (int j = 0; j < 64; j++) {
                float4 w = *(const float4*)(t0w1 + j * 56 + 4 * ct2);
                float a0 = E[j * 64 + 4 * rt2 + 0];
                float a1 = E[j * 64 + 4 * rt2 + 1];
                float a2 = E[j * 64 + 4 * rt2 + 2];
                float a3 = E[j * 64 + 4 * rt2 + 3];
                acc[0][0] += a0*w.x; acc[0][1] += a0*w.y; acc[0][2] += a0*w.z; acc[0][3] += a0*w.w;
                acc[1][0] += a1*w.x; acc[1][1] += a1*w.y; acc[1][2] += a1*w.z; acc[1][3] += a1*w.w;
                acc[2][0] += a2*w.x; acc[2][1] += a2*w.y; acc[2][2] += a2*w.z; acc[2][3] += a2*w.w;
                acc[3][0] += a3*w.x; acc[3][1] += a3*w.y; acc[3][2] += a3*w.z; acc[3][3] += a3*w.w;
            }
            #pragma unroll
            for (int i = 0; i < 4; i++)
                #pragma unroll
                for (int j = 0; j < 4; j++)
                    g_M0[(4 * rt2 + i) * 56 + 4 * ct2 + j] = acc[i][j];
        }
    } else {
        // M1[48][40]
        const int CT2 = 10;
        int rt2 = tid / CT2, ct2 = tid - rt2 * CT2;
        if (rt2 < 12) {
            float acc[4][4] = {};
            for (int j = 0; j < 48; j++) {
                float4 w = *(const float4*)(t1w1 + j * 40 + 4 * ct2);
                float a0 = E[j * 48 + 4 * rt2 + 0];
                float a1 = E[j * 48 + 4 * rt2 + 1];
                float a2 = E[j * 48 + 4 * rt2 + 2];
                float a3 = E[j * 48 + 4 * rt2 + 3];
                acc[0][0] += a0*w.x; acc[0][1] += a0*w.y; acc[0][2] += a0*w.z; acc[0][3] += a0*w.w;
                acc[1][0] += a1*w.x; acc[1][1] += a1*w.y; acc[1][2] += a1*w.z; acc[1][3] += a1*w.w;
                acc[2][0] += a2*w.x; acc[2][1] += a2*w.y; acc[2][2] += a2*w.z; acc[2][3] += a2*w.w;
                acc[3][0] += a3*w.x; acc[3][1] += a3*w.y; acc[3][2] += a3*w.z; acc[3][3] += a3*w.w;
            }
            #pragma unroll
            for (int i = 0; i < 4; i++)
                #pragma unroll
                for (int j = 0; j < 4; j++)
                    g_M1[(4 * rt2 + i) * 40 + 4 * ct2 + j] = acc[i][j];
        }
    }
}

// ===================== level scalar gain =======================================
__device__ __forceinline__ float level_g(float rf, float sqcf, float s_raw, float smin)
{
    float scale = fmaxf(s_raw, smin);
    float ut = scale * rf;
    float un = fmaxf(ut, 1e-7f);
    float th = tanhf(sqcf * un);
    float a  = th / (sqcf * un);
    float en = fmaxf(a * ut, 1e-7f);
    float maxn = 0.99999f / sqcf;
    float f  = fminf(1.0f, maxn / en);
    float xn = fmaxf(f * (a * ut), 1e-7f);
    float arg = fminf(sqcf * xn, 0.99999994f);
    double L = atanh((double)arg) / ((double)sqcf * (double)xn);
    return (float)(L * (double)f * (double)a * (double)scale / (double)(scale + 1e-7f));
}

// ===================== smem layout (floats) ====================================
#define OFF_M0   0
#define OFF_B1   3584
#define OFF_W2   3640
#define OFF_B2   6328
#define OFF_M1   6376
#define OFF_B1B  8296
#define OFF_W2B  8336
#define OFF_B2B  9616
#define OFF_WOUT 9648      /* 144 x 12 (cols padded) */
#define OFF_BOUT 11376
#define OFF_BF   11388
#define OFF_G    11452
#define OFF_V0   11516     /* 64 x 65 */
#define OFF_C    15676
/* GEMM region: xs[2][64][36] + ws[2][28][64] = 4608 + 3584 = 8192 floats */
#define OFF_XS   (OFF_C)
#define OFF_WS   (OFF_C + 4608)
/* Epilogue region (reuses GEMM region): */
#define OFF_H    (OFF_C)               /* h56 (64x56) / h40 (64x40) */
#define OFF_V1   (OFF_C + 3584)        /* 64 x 49 */
#define OFF_V2   (OFF_V1 + 3136)       /* 64 x 33 */
#define OFF_OUT  (OFF_V2 + 2112)       /* 64 x 12 */
#define SMEM_FLOATS (OFF_OUT + 768)
#define SMEM_BYTES (SMEM_FLOATS * 4)

#define KTILES 28   /* 28 tiles x 28 k = 784 */

// ===================== smem mat-mat helper (64 rows, 4x4 tiles) ================
__device__ __forceinline__ void matvec_tile(
    const float* __restrict__ in, int instr, int K,
    const float* __restrict__ W, int N,
    const float* __restrict__ bias,
    float* __restrict__ out, int outstr,
    bool relu, bool accum, int tid)
{
    const int CT = N >> 2;
    const int rt = tid / CT;
    if (rt >= 16) return;
    const int ct = tid - rt * CT;
    float acc[4][4];
    if (accum) {
        #pragma unroll
        for (int i = 0; i < 4; i++)
            #pragma unroll
            for (int j = 0; j < 4; j++)
                acc[i][j] = out[(4 * rt + i) * outstr + 4 * ct + j];
    } else {
        #pragma unroll
        for (int i = 0; i < 4; i++)
            #pragma unroll
            for (int j = 0; j < 4; j++) acc[i][j] = 0.f;
    }
    const float* inr0 = in + (4 * rt + 0) * instr;
    const float* inr1 = in + (4 * rt + 1) * instr;
    const float* inr2 = in + (4 * rt + 2) * instr;
    const float* inr3 = in + (4 * rt + 3) * instr;
    #pragma unroll 4
    for (int k = 0; k < K; k++) {
        float a0 = inr0[k], a1 = inr1[k], a2 = inr2[k], a3 = inr3[k];
        float4 w = *(const float4*)(W + k * N + 4 * ct);
        acc[0][0] += a0 * w.x; acc[0][1] += a0 * w.y; acc[0][2] += a0 * w.z; acc[0][3] += a0 * w.w;
        acc[1][0] += a1 * w.x; acc[1][1] += a1 * w.y; acc[1][2] += a1 * w.z; acc[1][3] += a1 * w.w;
        acc[2][0] += a2 * w.x; acc[2][1] += a2 * w.y; acc[2][2] += a2 * w.z; acc[2][3] += a2 * w.w;
        acc[3][0] += a3 * w.x; acc[3][1] += a3 * w.y; acc[3][2] += a3 * w.z; acc[3][3] += a3 * w.w;
    }
    #pragma unroll
    for (int i = 0; i < 4; i++)
        #pragma unroll
        for (int j = 0; j < 4; j++) {
            float v = acc[i][j];
            if (bias) v += bias[4 * ct + j];
            if (relu) v = fmaxf(v, 0.f);
            out[(4 * rt + i) * outstr + 4 * ct + j] = v;
        }
}

// ===================== main fused kernel: 64 rows / block ======================
__global__ void __launch_bounds__(THREADS) main_kernel(
    const float* __restrict__ x,
    const float* __restrict__ s0p, const float* __restrict__ s1p, const float* __restrict__ s2p,
    const float* __restrict__ t0b1, const float* __restrict__ t0w2, const float* __restrict__ t0b2,
    const float* __restrict__ t1b1, const float* __restrict__ t1w2, const float* __restrict__ t1b2,
    const float* __restrict__ Wout, const float* __restrict__ bout,
    float* __restrict__ out, int B)
{
    extern __shared__ float sm[];
    const int tid = threadIdx.x;
    const int row0 = blockIdx.x * 64;

    // ---- issue first GEMM tile loads (cp.async, double-buffered) ------------
    // tile layout: xs[64][36] row-major (16B-aligned rows), ws[28][64]
    {
        unsigned xs_s = (unsigned)__cvta_generic_to_shared(sm + OFF_XS);
        unsigned ws_s = (unsigned)__cvta_generic_to_shared(sm + OFF_WS);
        for (int q = tid; q < 896; q += THREADS) {
            if (q < 448) {
                int r = q / 7, c4 = (q - r * 7) * 4;
                int gr = row0 + r;
                if (gr < B) {
                    CP16(xs_s + (r * 36 + c4) * 4, x + (size_t)gr * 784 + c4);
                } else {
                    *(float4*)(sm + OFF_XS + r * 36 + c4) = make_float4(0.f, 0.f, 0.f, 0.f);
                }
            } else {
                int q2 = q - 448;
                int k = q2 >> 4, c4 = (q2 & 15) * 4;
                CP16(ws_s + (k * 64 + c4) * 4, g_Wfold + k * 64 + c4);
            }
        }
        CP_COMMIT();
    }

    // ---- load small weights into smem (overlaps with tile-0 cp.async) -------
    for (int i = tid; i < 3584; i += THREADS) sm[OFF_M0 + i] = g_M0[i];
    for (int i = tid; i < 56;   i += THREADS) sm[OFF_B1 + i] = t0b1[i];
    for (int i = tid; i < 2688; i += THREADS) sm[OFF_W2 + i] = t0w2[i];
    for (int i = tid; i < 48;   i += THREADS) sm[OFF_B2 + i] = t0b2[i];
    for (int i = tid; i < 1920; i += THREADS) sm[OFF_M1 + i] = g_M1[i];
    for (int i = tid; i < 40;   i += THREADS) sm[OFF_B1B + i] = t1b1[i];
    for (int i = tid; i < 1280; i += THREADS) sm[OFF_W2B + i] = t1w2[i];
    for (int i = tid; i < 32;   i += THREADS) sm[OFF_B2B + i] = t1b2[i];
    for (int i = tid; i < 144 * 12; i += THREADS) {
        int k = i / 12, c = i - k * 12;
        sm[OFF_WOUT + i] = (c < 10) ? Wout[k * 10 + c] : 0.f;
    }
    for (int i = tid; i < 12; i += THREADS) sm[OFF_BOUT + i] = (i < 10) ? bout[i] : 0.f;
    for (int i = tid; i < 64; i += THREADS) sm[OFF_BF + i] = g_bfold[i];

    // ---- big GEMM: v = x @ Wfold + bfold  (64x784 @ 784x64) -----------------
    float acc[4][4];
    #pragma unroll
    for (int i = 0; i < 4; i++)
        #pragma unroll
        for (int j = 0; j < 4; j++) acc[i][j] = 0.f;
    const int ty = tid >> 4, tx = tid & 15;

    for (int kt = 0; kt < KTILES; kt++) {
        const int cur = kt & 1;
        if (kt < KTILES - 1) {
            // prefetch next tile into the other buffer
            const int kbase = (kt + 1) * 28;
            const int nbuf = cur ^ 1;
            unsigned xs_s = (unsigned)__cvta_generic_to_shared(sm + OFF_XS + nbuf * 2304);
            unsigned ws_s = (unsigned)__cvta_generic_to_shared(sm + OFF_WS + nbuf * 1792);
            for (int q = tid; q < 896; q += THREADS) {
                if (q < 448) {
                    int r = q / 7, c4 = (q - r * 7) * 4;
                    int gr = row0 + r;
                    if (gr < B) {
                        CP16(xs_s + (r * 36 + c4) * 4, x + (size_t)gr * 784 + kbase + c4);
                    } else {
                        *(float4*)(sm + OFF_XS + nbuf * 2304 + r * 36 + c4) = make_float4(0.f, 0.f, 0.f, 0.f);
                    }
                } else {
                    int q2 = q - 448;
                    int k = q2 >> 4, c4 = (q2 & 15) * 4;
                    CP16(ws_s + (k * 64 + c4) * 4, g_Wfold + (kbase + k) * 64 + c4);
                }
            }
            CP_COMMIT();
            CP_WAIT1();
        } else {
            CP_WAIT0();
        }
        __syncthreads();

        const float* xsb = sm + OFF_XS + cur * 2304 + (ty << 2) * 36;
        const float* wsb = sm + OFF_WS + cur * 1792 + (tx << 2);
        #pragma unroll
        for (int k = 0; k < 28; k++) {
            float4 b = *(const float4*)(wsb + k * 64);
            float a0 = xsb[k];
            float a1 = xsb[36 + k];
            float a2 = xsb[72 + k];
            float a3 = xsb[108 + k];
            acc[0][0] += a0 * b.x; acc[0][1] += a0 * b.y; acc[0][2] += a0 * b.z; acc[0][3] += a0 * b.w;
            acc[1][0] += a1 * b.x; acc[1][1] += a1 * b.y; acc[1][2] += a1 * b.z; acc[1][3] += a1 * b.w;
            acc[2][0] += a2 * b.x; acc[2][1] += a2 * b.y; acc[2][2] += a2 * b.z; acc[2][3] += a2 * b.w;
            acc[3][0] += a3 * b.x; acc[3][1] += a3 * b.y; acc[3][2] += a3 * b.z; acc[3][3] += a3 * b.w;
        }
        __syncthreads();
    }

    #pragma unroll
    for (int i = 0; i < 4; i++)
        #pragma unroll
        for (int j = 0; j < 4; j++)
            sm[OFF_V0 + (4 * ty + i) * 65 + 4 * tx + j] = acc[i][j] + sm[OFF_BF + 4 * tx + j];
    __syncthreads();

    const float s0 = s0p[0], s1 = s1p[0], s2 = s2p[0];

    // ---- level 0 (c=1.0) -----------------------------------------------------
    if (tid < 64) {
        double r2 = 0.0;
        for (int k = 0; k < 64; k++) { float d = sm[OFF_V0 + tid * 65 + k]; r2 += (double)d * (double)d; }
        sm[OFF_G + tid] = level_g((float)sqrt(r2), 1.0f, s0, 1e-4f);
    }
    __syncthreads();
    for (int i = tid; i < 64 * 64; i += THREADS) {
        int r = i >> 6;
        sm[OFF_V0 + r * 65 + (i & 63)] *= sm[OFF_G + r];
    }
    __syncthreads();

    // ---- MLP0 (rotation folded into M0) -------------------------------------
    matvec_tile(sm + OFF_V0, 65, 64, sm + OFF_M0, 56, sm + OFF_B1, sm + OFF_H, 56, true,  false, tid);
    __syncthreads();
    matvec_tile(sm + OFF_H, 56, 56, sm + OFF_W2, 48, sm + OFF_B2, sm + OFF_V1, 49, false, false, tid);
    __syncthreads();

    // ---- level 1 (c=0.8) -----------------------------------------------------
    if (tid < 64) {
        double r2 = 0.0;
        for (int k = 0; k < 48; k++) { float d = sm[OFF_V1 + tid * 49 + k]; r2 += (double)d * (double)d; }
        sm[OFF_G + tid] = level_g((float)sqrt(r2), sqrtf(0.8f), s1, 1e-5f);
    }
    __syncthreads();
    for (int i = tid; i < 64 * 48; i += THREADS) {
        int r = i / 48;
        sm[OFF_V1 + r * 49 + (i - r * 48)] *= sm[OFF_G + r];
    }
    __syncthreads();

    // ---- MLP1 ----------------------------------------------------------------
    matvec_tile(sm + OFF_V1, 49, 48, sm + OFF_M1, 40, sm + OFF_B1B, sm + OFF_H, 40, true,  false, tid);
    __syncthreads();
    matvec_tile(sm + OFF_H, 40, 40, sm + OFF_W2B, 32, sm + OFF_B2B, sm + OFF_V2, 33, false, false, tid);
    __syncthreads();

    // ---- level 2 (c=1.2) -----------------------------------------------------
    if (tid < 64) {
        double r2 = 0.0;
        for (int k = 0; k < 32; k++) { float d = sm[OFF_V2 + tid * 33 + k]; r2 += (double)d * (double)d; }
        sm[OFF_G + tid] = level_g((float)sqrt(r2), sqrtf(1.2f), s2, 1e-6f);
    }
    __syncthreads();
    for (int i = tid; i < 64 * 32; i += THREADS) {
        int r = i >> 5;
        sm[OFF_V2 + r * 33 + (i & 31)] *= sm[OFF_G + r];
    }
    __syncthreads();

    // ---- final projection: out = [v0 v1 v2] @ Wout + bout ---------------------
    matvec_tile(sm + OFF_V0, 65, 64, sm + OFF_WOUT,            12, sm + OFF_BOUT, sm + OFF_OUT, 12, false, false, tid);
    __syncthreads();
    matvec_tile(sm + OFF_V1, 49, 48, sm + OFF_WOUT + 64 * 12,  12, (const float*)0, sm + OFF_OUT, 12, false, true, tid);
    __syncthreads();
    matvec_tile(sm + OFF_V2, 33, 32, sm + OFF_WOUT + 112 * 12, 12, (const float*)0, sm + OFF_OUT, 12, false, true, tid);
    __syncthreads();

    for (int i = tid; i < 640; i += THREADS) {
        int r = i / 10, c = i - r * 10;
        int gr = row0 + r;
        if (gr < B) out[(size_t)gr * 10 + c] = sm[OFF_OUT + r * 12 + c];
    }
}

// =========================== launch ===========================================
extern "C" void kernel_launch(void* const* d_in, const int* in_sizes, int n_in,
                              void* d_out, int out_size)
{
    const float* x     = (const float*)d_in[0];
    const float* W_in  = (const float*)d_in[1];
    const float* b_in  = (const float*)d_in[2];
    const float* W_tan = (const float*)d_in[3];
    const float* b_tan = (const float*)d_in[4];
    const float* s0    = (const float*)d_in[5];
    const float* s1    = (const float*)d_in[6];
    const float* s2    = (const float*)d_in[7];
    // d_in[8], d_in[9]: tp0/tp1 boundary params — dead path, unused
    const float* A0    = (const float*)d_in[10];
    const float* A1    = (const float*)d_in[11];
    const float* t0w1  = (const float*)d_in[12];
    const float* t0b1  = (const float*)d_in[13];
    const float* t0w2  = (const float*)d_in[14];
    const float* t0b2  = (const float*)d_in[15];
    const float* t1w1  = (const float*)d_in[16];
    const float* t1b1  = (const float*)d_in[17];
    const float* t1w2  = (const float*)d_in[18];
    const float* t1b2  = (const float*)d_in[19];
    const float* Wout  = (const float*)d_in[20];
    const float* bout  = (const float*)d_in[21];
    float* out = (float*)d_out;

    const int B = in_sizes[0] / 784;

    cudaFuncSetAttribute(main_kernel, cudaFuncAttributeMaxDynamicSharedMemorySize, SMEM_BYTES);

    prep_kernel<<<2 + (784 * 64 + THREADS - 1) / THREADS, THREADS>>>(
        A0, A1, t0w1, t1w1, W_in, b_in, W_tan, b_tan);
    main_kernel<<<(B + 63) / 64, THREADS, SMEM_BYTES>>>(
        x, s0, s1, s2, t0b1, t0w2, t0b2, t1b1, t1w2, t1b2, Wout, bout, out, B);
}